// round 4
// baseline (speedup 1.0000x reference)
#include <cuda_runtime.h>
#include <cstdint>

// Problem constants
#define NPC      8000     // 64000 // 8
#define NPC_PAD  8192
#define NREF     10000    // 80000 // 8
#define TN       512      // pc tile per block
#define TM       500      // ref tile per block
#define GRID_REF 20       // 10000 / 500
#define GRID_PC  16       // 8192 / 512
#define NBLOCKS  (GRID_REF * GRID_PC)   // 320
#define NTHREADS 128
#define P        4        // pc points per thread (phase A) / refs per thread (phase B)

// Scratch (no cudaMalloc allowed)
__device__ float2   g_pc[NPC_PAD];
__device__ float2   g_ref[NREF];
__device__ unsigned g_min1[NPC_PAD];
__device__ unsigned g_min2[NREF];
__device__ float    g_sums[2];

// ---- packed f32x2 helpers (Blackwell; ptxas never auto-fuses these) ----
static __device__ __forceinline__ unsigned long long pk2(float lo, float hi) {
    unsigned long long r;
    asm("mov.b64 %0, {%1, %2};" : "=l"(r) : "f"(lo), "f"(hi));
    return r;
}
static __device__ __forceinline__ void upk2(unsigned long long v, float& lo, float& hi) {
    asm("mov.b64 {%0, %1}, %2;" : "=f"(lo), "=f"(hi) : "l"(v));
}
static __device__ __forceinline__ unsigned long long vadd2(unsigned long long a, unsigned long long b) {
    unsigned long long r;
    asm("add.rn.f32x2 %0, %1, %2;" : "=l"(r) : "l"(a), "l"(b));
    return r;
}
static __device__ __forceinline__ unsigned long long vmul2(unsigned long long a, unsigned long long b) {
    unsigned long long r;
    asm("mul.rn.f32x2 %0, %1, %2;" : "=l"(r) : "l"(a), "l"(b));
    return r;
}
static __device__ __forceinline__ unsigned long long vfma2(unsigned long long a, unsigned long long b,
                                                           unsigned long long c) {
    unsigned long long r;
    asm("fma.rn.f32x2 %0, %1, %2, %3;" : "=l"(r) : "l"(a), "l"(b), "l"(c));
    return r;
}

#define FINF_BITS 0x7F800000u
#define PAD_VAL   1e18f

// ---------------------------------------------------------------------------
// K1: init min arrays + gather subsampled points (matches jnp.linspace fp32
//     semantics: delta = (n-1)/(num-1) in fp32, idx = trunc(i * delta))
// ---------------------------------------------------------------------------
__global__ void k_init(const float* __restrict__ in0, const float* __restrict__ in1) {
    int i = blockIdx.x * blockDim.x + threadIdx.x;
    const float D1 = 63999.0f / 7999.0f;   // compile-time fp32 rn
    const float D2 = 79999.0f / 9999.0f;

    if (i < NPC_PAD) {
        g_min1[i] = FINF_BITS;
        float2 p;
        if (i < NPC) {
            int s = (int)((float)i * D1);
            p.x = in0[2 * s];
            p.y = in0[2 * s + 1];
        } else {
            p.x = PAD_VAL; p.y = PAD_VAL;
        }
        g_pc[i] = p;
    }
    if (i < NREF) {
        g_min2[i] = FINF_BITS;
        int s = (int)((float)i * D2);
        float2 r;
        r.x = in1[2 * s];
        r.y = in1[2 * s + 1];
        g_ref[i] = r;
    }
    if (i == 0) { g_sums[0] = 0.0f; g_sums[1] = 0.0f; }
}

// ---------------------------------------------------------------------------
// K2: main pair kernel. Block (cx, cy) covers pc tile cy x ref tile cx.
//     Phase A: threads own 4 pc points, sweep ref tile from shared -> min1.
//     Phase B: threads own 4 ref points, sweep pc tile from shared -> min2.
//     Shared tile holds NEGATED coords so diff = add.f32x2.
// ---------------------------------------------------------------------------
__global__ void __launch_bounds__(NTHREADS) k_main() {
    __shared__ float2 stile[TN];   // 512 float2 = 4KB, reused both phases

    int b  = blockIdx.x;
    int cx = b % GRID_REF;         // ref chunk
    int cy = b / GRID_REF;         // pc tile
    int t  = threadIdx.x;
    int refBase = cx * TM;
    int pcBase  = cy * TN;

    const float FINF = __uint_as_float(FINF_BITS);

    // ---- Phase A: min over refs for each owned pc point ----
    for (int s = t; s < TM; s += NTHREADS) {
        float2 r = g_ref[refBase + s];
        stile[s] = make_float2(-r.x, -r.y);
    }
    __syncthreads();

    {
        int myPc = pcBase + t * P;
        float2 p0 = g_pc[myPc + 0], p1 = g_pc[myPc + 1];
        float2 p2 = g_pc[myPc + 2], p3 = g_pc[myPc + 3];
        unsigned long long ax0 = pk2(p0.x, p1.x), ay0 = pk2(p0.y, p1.y);
        unsigned long long ax1 = pk2(p2.x, p3.x), ay1 = pk2(p2.y, p3.y);
        float m0 = FINF, m1 = FINF, m2 = FINF, m3 = FINF;

#pragma unroll 4
        for (int j = 0; j < TM; j++) {
            float2 nr = stile[j];
            unsigned long long nx = pk2(nr.x, nr.x);
            unsigned long long ny = pk2(nr.y, nr.y);
            unsigned long long dx0 = vadd2(ax0, nx), dy0 = vadd2(ay0, ny);
            unsigned long long d0  = vfma2(dx0, dx0, vmul2(dy0, dy0));
            unsigned long long dx1 = vadd2(ax1, nx), dy1 = vadd2(ay1, ny);
            unsigned long long d1  = vfma2(dx1, dx1, vmul2(dy1, dy1));
            float f0, f1, f2, f3;
            upk2(d0, f0, f1);
            upk2(d1, f2, f3);
            m0 = fminf(m0, f0); m1 = fminf(m1, f1);
            m2 = fminf(m2, f2); m3 = fminf(m3, f3);
        }
        atomicMin(&g_min1[myPc + 0], __float_as_uint(m0));
        atomicMin(&g_min1[myPc + 1], __float_as_uint(m1));
        atomicMin(&g_min1[myPc + 2], __float_as_uint(m2));
        atomicMin(&g_min1[myPc + 3], __float_as_uint(m3));
    }

    __syncthreads();   // phase A shared reads done before overwrite

    // ---- Phase B: min over pc for each owned ref point ----
    for (int s = t; s < TN; s += NTHREADS) {
        float2 p = g_pc[pcBase + s];
        stile[s] = make_float2(-p.x, -p.y);
    }
    __syncthreads();

    {
        int myRefLocal = t * P;                 // TM=500 = 125 threads * 4, exact
        bool act = (myRefLocal + P) <= TM;      // t < 125 active
        float2 r0, r1, r2, r3;
        if (act) {
            r0 = g_ref[refBase + myRefLocal + 0];
            r1 = g_ref[refBase + myRefLocal + 1];
            r2 = g_ref[refBase + myRefLocal + 2];
            r3 = g_ref[refBase + myRefLocal + 3];
        } else {
            r0 = r1 = r2 = r3 = make_float2(PAD_VAL, PAD_VAL);
        }
        unsigned long long bx0 = pk2(r0.x, r1.x), by0 = pk2(r0.y, r1.y);
        unsigned long long bx1 = pk2(r2.x, r3.x), by1 = pk2(r2.y, r3.y);
        float m0 = FINF, m1 = FINF, m2 = FINF, m3 = FINF;

#pragma unroll 4
        for (int i = 0; i < TN; i++) {
            float2 np = stile[i];
            unsigned long long nx = pk2(np.x, np.x);
            unsigned long long ny = pk2(np.y, np.y);
            unsigned long long dx0 = vadd2(bx0, nx), dy0 = vadd2(by0, ny);
            unsigned long long d0  = vfma2(dx0, dx0, vmul2(dy0, dy0));
            unsigned long long dx1 = vadd2(bx1, nx), dy1 = vadd2(by1, ny);
            unsigned long long d1  = vfma2(dx1, dx1, vmul2(dy1, dy1));
            float f0, f1, f2, f3;
            upk2(d0, f0, f1);
            upk2(d1, f2, f3);
            m0 = fminf(m0, f0); m1 = fminf(m1, f1);
            m2 = fminf(m2, f2); m3 = fminf(m3, f3);
        }
        if (act) {
            atomicMin(&g_min2[refBase + myRefLocal + 0], __float_as_uint(m0));
            atomicMin(&g_min2[refBase + myRefLocal + 1], __float_as_uint(m1));
            atomicMin(&g_min2[refBase + myRefLocal + 2], __float_as_uint(m2));
            atomicMin(&g_min2[refBase + myRefLocal + 3], __float_as_uint(m3));
        }
    }
}

// ---------------------------------------------------------------------------
// K3: sqrt + partial sums of both min arrays
// ---------------------------------------------------------------------------
__global__ void k_reduce() {
    int i      = blockIdx.x * blockDim.x + threadIdx.x;
    int stride = gridDim.x * blockDim.x;
    float s1 = 0.0f, s2 = 0.0f;
    for (int e = i; e < NPC + NREF; e += stride) {
        if (e < NPC) s1 += sqrtf(__uint_as_float(g_min1[e]));
        else         s2 += sqrtf(__uint_as_float(g_min2[e - NPC]));
    }
    // warp reduction
#pragma unroll
    for (int off = 16; off > 0; off >>= 1) {
        s1 += __shfl_down_sync(0xFFFFFFFFu, s1, off);
        s2 += __shfl_down_sync(0xFFFFFFFFu, s2, off);
    }
    if ((threadIdx.x & 31) == 0) {
        if (s1 != 0.0f) atomicAdd(&g_sums[0], s1);
        if (s2 != 0.0f) atomicAdd(&g_sums[1], s2);
    }
}

// ---------------------------------------------------------------------------
// K4: final scalar
// ---------------------------------------------------------------------------
__global__ void k_final(float* __restrict__ out) {
    out[0] = (g_sums[0] * (1.0f / NPC) + g_sums[1] * (1.0f / NREF)) * 0.5f;
}

extern "C" void kernel_launch(void* const* d_in, const int* in_sizes, int n_in,
                              void* d_out, int out_size) {
    const float* in0 = (const float*)d_in[0];   // img_render_points, 128000 floats
    const float* in1 = (const float*)d_in[1];   // ref point cloud,   160000 floats
    float* out = (float*)d_out;

    k_init<<<40, 256>>>(in0, in1);
    k_main<<<NBLOCKS, NTHREADS>>>();
    k_reduce<<<36, 256>>>();
    k_final<<<1, 1>>>(out);
}